// round 4
// baseline (speedup 1.0000x reference)
#include <cuda_runtime.h>
#include <math.h>

#define N 1024
#define H 8
#define OBS_LEN 8
#define PRED_LEN 12

typedef unsigned long long u64;

#define ABSMASK 0x7fffffff7fffffffULL

// ---------------- scratch (device globals; no allocation) ----------------
__device__ float g_h[N * H];
__device__ float g_c[N * H];
__device__ float g_posA[N * 64];       // posA[i][k] = A[k] . pos_i
__device__ float g_pos[N * 2];         // raw last positions
__device__ u64   g_ud[N * 64];         // (u,u) duplicated pairs, per i
__device__ float g_v[2][64 * N];       // v_j, k-major, double-buffered
__device__ float g_linvh[2][8 * N];    // 0.5*Sum_k v_jk w_ko, o-major, double-buffered
__device__ float g_lin[N * 8];         // 0.5*Sum_k u_ik w_ko
__device__ u64   g_W2d[512];           // [k][o] = (0.5*w_ko, 0.5*w_ko)
__device__ float g_A[128];             // A[k][2] = W1[:, :32] @ Wsp
__device__ float g_dconst[64];         // d = b1 + W1[:, :32] @ bsp
__device__ float g_Ph[16];             // 0.5 * W2 @ A        [8][2]
__device__ float g_Qh[64];             // 0.5 * W2 @ C(h_i)   [8][8]
__device__ float g_Rh[64];             // 0.5 * W2 @ B(h_j)   [8][8]
__device__ float g_Sh[8];              // 0.5 * W2 @ d

// ---------------- packed f32x2 helpers ----------------
__device__ __forceinline__ u64 pack2(float lo, float hi) {
    u64 r; asm("mov.b64 %0, {%1, %2};" : "=l"(r) : "f"(lo), "f"(hi)); return r;
}
__device__ __forceinline__ void unpack2(u64 v, float& lo, float& hi) {
    asm("mov.b64 {%0, %1}, %2;" : "=f"(lo), "=f"(hi) : "l"(v));
}
__device__ __forceinline__ void ffma2(u64& d, u64 a, u64 b) {
    asm("fma.rn.f32x2 %0, %1, %2, %0;" : "+l"(d) : "l"(a), "l"(b));
}
__device__ __forceinline__ u64 add2(u64 a, u64 b) {
    u64 r; asm("add.rn.f32x2 %0, %1, %2;" : "=l"(r) : "l"(a), "l"(b)); return r;
}

__device__ __forceinline__ float sigm(float x) { return 1.f / (1.f + expf(-x)); }

// ---------------- LSTM cell helper ----------------
__device__ __forceinline__ void lstm_step(const float* x, float* h, float* c,
                                          const float* sWih, const float* sWhh,
                                          const float* sb) {
    float gates[32];
    #pragma unroll
    for (int g = 0; g < 32; g++) {
        float a = sb[g];
        #pragma unroll
        for (int m = 0; m < 16; m++) a = fmaf(sWih[g * 16 + m], x[m], a);
        #pragma unroll
        for (int q = 0; q < 8; q++) a = fmaf(sWhh[g * 8 + q], h[q], a);
        gates[g] = a;
    }
    #pragma unroll
    for (int q = 0; q < 8; q++) {
        float ig = sigm(gates[q]);
        float fg = sigm(gates[8 + q]);
        float gg = tanhf(gates[16 + q]);
        float og = sigm(gates[24 + q]);
        float cn = fg * c[q] + ig * gg;
        c[q] = cn;
        h[q] = og * tanhf(cn);
    }
}

// ---------------- setup: A, d, W2-dup table, P/Q/R/S ----------------
__global__ void k_setup(const float* __restrict__ W1, const float* __restrict__ b1,
                        const float* __restrict__ Wsp, const float* __restrict__ bsp,
                        const float* __restrict__ W2) {
    __shared__ float sA[128], sd[64];
    int t = threadIdx.x;   // 64 threads
    {
        int k = t;
        float a0 = 0.f, a1 = 0.f, dd = b1[k];
        #pragma unroll 4
        for (int e = 0; e < 32; e++) {
            float w = W1[k * 48 + e];
            a0 = fmaf(w, Wsp[e * 2 + 0], a0);
            a1 = fmaf(w, Wsp[e * 2 + 1], a1);
            dd = fmaf(w, bsp[e], dd);
        }
        sA[k * 2 + 0] = a0; sA[k * 2 + 1] = a1; sd[k] = dd;
        g_A[k * 2 + 0] = a0; g_A[k * 2 + 1] = a1; g_dconst[k] = dd;
        #pragma unroll
        for (int o = 0; o < 8; o++) {
            float w = 0.5f * W2[o * 64 + k];
            g_W2d[k * 8 + o] = pack2(w, w);
        }
    }
    __syncthreads();
    if (t < 8) {
        int o = t;
        float p0 = 0.f, p1 = 0.f, s = 0.f;
        float q[8], r[8];
        #pragma unroll
        for (int z = 0; z < 8; z++) { q[z] = 0.f; r[z] = 0.f; }
        for (int k = 0; k < 64; k++) {
            float w = 0.5f * W2[o * 64 + k];
            p0 = fmaf(w, sA[k * 2 + 0], p0);
            p1 = fmaf(w, sA[k * 2 + 1], p1);
            s  = fmaf(w, sd[k], s);
            #pragma unroll
            for (int z = 0; z < 8; z++) {
                q[z] = fmaf(w, W1[k * 48 + 40 + z], q[z]);  // C block (h_i)
                r[z] = fmaf(w, W1[k * 48 + 32 + z], r[z]);  // B block (h_j)
            }
        }
        g_Ph[o * 2 + 0] = p0; g_Ph[o * 2 + 1] = p1; g_Sh[o] = s;
        #pragma unroll
        for (int z = 0; z < 8; z++) { g_Qh[o * 8 + z] = q[z]; g_Rh[o * 8 + z] = r[z]; }
    }
}

// ---------------- encoder: 8 LSTM steps + first decoder LSTM + u/v/lin ----------------
__global__ void __launch_bounds__(128) k_encoder(
        const float* __restrict__ obs_traj, const float* __restrict__ obs_pos,
        const float* __restrict__ h0, const float* __restrict__ c0,
        const float* __restrict__ We, const float* __restrict__ be,
        const float* __restrict__ WihT, const float* __restrict__ WhhT,
        const float* __restrict__ bihT, const float* __restrict__ bhhT,
        const float* __restrict__ bd,
        const float* __restrict__ WihP, const float* __restrict__ WhhP,
        const float* __restrict__ bihP, const float* __restrict__ bhhP,
        const float* __restrict__ W1) {
    __shared__ float sWe[32], sbe[16], sWihT[512], sWhhT[256], sbT[32];
    __shared__ float sWihP[512], sWhhP[256], sbP[32], sbd[16];
    __shared__ float sB[512], sC[512], sA[128], sd[64];
    __shared__ float sPh[16], sQh[64], sRh[64], sSh[8];
    int tid = threadIdx.x;
    for (int idx = tid; idx < 32; idx += 128) sWe[idx] = We[idx];
    for (int idx = tid; idx < 16; idx += 128) { sbe[idx] = be[idx]; sbd[idx] = bd[idx];
                                               sPh[idx] = g_Ph[idx]; }
    for (int idx = tid; idx < 512; idx += 128) { sWihT[idx] = WihT[idx]; sWihP[idx] = WihP[idx]; }
    for (int idx = tid; idx < 256; idx += 128) { sWhhT[idx] = WhhT[idx]; sWhhP[idx] = WhhP[idx]; }
    for (int idx = tid; idx < 32; idx += 128) { sbT[idx] = bihT[idx] + bhhT[idx];
                                               sbP[idx] = bihP[idx] + bhhP[idx]; }
    for (int idx = tid; idx < 512; idx += 128) {
        int k = idx >> 3, q = idx & 7;
        sB[idx] = W1[k * 48 + 32 + q];
        sC[idx] = W1[k * 48 + 40 + q];
    }
    for (int idx = tid; idx < 128; idx += 128) sA[idx] = g_A[idx];
    for (int idx = tid; idx < 64; idx += 128) { sd[idx] = g_dconst[idx];
                                               sQh[idx] = g_Qh[idx]; sRh[idx] = g_Rh[idx]; }
    if (tid < 8) sSh[tid] = g_Sh[tid];
    __syncthreads();

    int i = blockIdx.x * 128 + tid;

    float h[8], c[8];
    #pragma unroll
    for (int q = 0; q < 8; q++) { h[q] = h0[i * 8 + q]; c[q] = c0[i * 8 + q]; }

    for (int t = 0; t < OBS_LEN; t++) {
        float px = obs_traj[(t * N + i) * 2 + 0];
        float py = obs_traj[(t * N + i) * 2 + 1];
        float x[16];
        #pragma unroll
        for (int m = 0; m < 16; m++)
            x[m] = fmaxf(fmaf(sWe[m * 2 + 0], px, fmaf(sWe[m * 2 + 1], py, sbe[m])), 0.f);
        lstm_step(x, h, c, sWihT, sWhhT, sbT);
    }

    // first decoder step: context=0, output=0 -> x = relu(bd)
    float x[16];
    #pragma unroll
    for (int m = 0; m < 16; m++) x[m] = fmaxf(sbd[m], 0.f);
    #pragma unroll
    for (int q = 0; q < 8; q++) c[q] = 0.f;
    lstm_step(x, h, c, sWihP, sWhhP, sbP);

    #pragma unroll
    for (int q = 0; q < 8; q++) { g_h[i * 8 + q] = h[q]; g_c[i * 8 + q] = c[q]; }

    float qx = obs_pos[((OBS_LEN - 1) * N + i) * 2 + 0];
    float qy = obs_pos[((OBS_LEN - 1) * N + i) * 2 + 1];
    g_pos[i * 2 + 0] = qx;
    g_pos[i * 2 + 1] = qy;

    #pragma unroll 4
    for (int k = 0; k < 64; k++) {
        float pa = fmaf(sA[k * 2 + 0], qx, sA[k * 2 + 1] * qy);
        g_posA[i * 64 + k] = pa;
        float uu = pa, vv = sd[k] - pa;
        #pragma unroll
        for (int q = 0; q < 8; q++) {
            uu = fmaf(h[q], sC[k * 8 + q], uu);
            vv = fmaf(h[q], sB[k * 8 + q], vv);
        }
        g_ud[i * 64 + k] = pack2(uu, uu);
        g_v[0][k * N + i] = vv;
    }

    // linear halves: lin = Ph.pos + Qh.h  ;  linvh = Sh - Ph.pos + Rh.h
    #pragma unroll
    for (int o = 0; o < 8; o++) {
        float pp = fmaf(sPh[o * 2 + 0], qx, sPh[o * 2 + 1] * qy);
        float lin = pp, lvv = sSh[o] - pp;
        #pragma unroll
        for (int q = 0; q < 8; q++) {
            lin = fmaf(sQh[o * 8 + q], h[q], lin);
            lvv = fmaf(sRh[o * 8 + q], h[q], lvv);
        }
        g_lin[i * 8 + o] = lin;
        g_linvh[0][o * N + i] = lvv;
    }
}

// ---------------- pooling + heads + next decoder step ----------------
__global__ void __launch_bounds__(256, 4) k_pool(
        const int* __restrict__ nei, const float* __restrict__ eps,
        const float* __restrict__ b2,
        const float* __restrict__ Wm, const float* __restrict__ bm,
        const float* __restrict__ Wv, const float* __restrict__ bv,
        const float* __restrict__ Wd, const float* __restrict__ bd,
        const float* __restrict__ WihP, const float* __restrict__ WhhP,
        const float* __restrict__ bihP, const float* __restrict__ bhhP,
        const float* __restrict__ W1,
        float* __restrict__ out, int t) {
    __shared__ u64 sud[64];        // (u,u) pairs for this i
    __shared__ u64 sW2p[512];      // (0.5w, 0.5w) per [k][o]
    __shared__ float sbase[8];     // g_lin + b2
    __shared__ float red[64];
    __shared__ float sph[8], spos[2], sx[16], sgate[32], sh[8];
    __shared__ float sPh[16], sQh[64], sRh[64], sSh[8];

    int i = blockIdx.x;
    int tid = threadIdx.x;

    if (tid < 64) sud[tid] = g_ud[i * 64 + tid];
    for (int idx = tid; idx < 512; idx += 256) sW2p[idx] = g_W2d[idx];
    if (tid < 8) sbase[tid] = g_lin[i * 8 + tid] + b2[tid];
    if (tid >= 64 && tid < 80)  sPh[tid - 64] = g_Ph[tid - 64];
    if (tid >= 80 && tid < 144) sQh[tid - 80] = g_Qh[tid - 80];
    if (tid >= 144 && tid < 208) sRh[tid - 144] = g_Rh[tid - 144];
    if (tid >= 208 && tid < 216) sSh[tid - 208] = g_Sh[tid - 208];
    __syncthreads();

    // thread handles j = 4*tid .. 4*tid+3
    u64 acc01[8], acc23[8];
    #pragma unroll
    for (int o = 0; o < 8; o++) { acc01[o] = 0ull; acc23[o] = 0ull; }

    const ulonglong2* vbase = (const ulonglong2*)(g_v[t & 1]);
    #pragma unroll 4
    for (int k = 0; k < 64; k++) {
        ulonglong2 vp = vbase[k * (N / 4) + tid];
        u64 ud = sud[k];
        u64 a01 = add2(ud, vp.x) & ABSMASK;
        u64 a23 = add2(ud, vp.y) & ABSMASK;
        const u64* wr = sW2p + k * 8;
        #pragma unroll
        for (int o = 0; o < 4; o++) {
            u64 w = wr[o];
            ffma2(acc01[o], a01, w);
            ffma2(acc23[o], a23, w);
        }
        #pragma unroll
        for (int o = 4; o < 8; o++) {
            u64 w = wr[o];
            ffma2(acc01[o], a01, w);
            ffma2(acc23[o], a23, w);
        }
    }

    // epilogue: pool_pre = base(i,o) + linvh(j,o) + abs_acc ; relu; masked max
    const int4 msk = ((const int4*)(nei + (size_t)t * N * N + (size_t)i * N))[tid];
    const float* lvb = g_linvh[t & 1];
    float mx[8];
    #pragma unroll
    for (int o = 0; o < 8; o++) {
        float4 lv = ((const float4*)(lvb + o * N))[tid];
        float a0, a1, a2, a3;
        unpack2(acc01[o], a0, a1);
        unpack2(acc23[o], a2, a3);
        float bo = sbase[o];
        float m = 0.f;
        if (msk.x > 0) m = fmaxf(m, fmaxf(bo + lv.x + a0, 0.f));
        if (msk.y > 0) m = fmaxf(m, fmaxf(bo + lv.y + a1, 0.f));
        if (msk.z > 0) m = fmaxf(m, fmaxf(bo + lv.z + a2, 0.f));
        if (msk.w > 0) m = fmaxf(m, fmaxf(bo + lv.w + a3, 0.f));
        mx[o] = m;
    }

    #pragma unroll
    for (int off = 16; off > 0; off >>= 1)
        #pragma unroll
        for (int o = 0; o < 8; o++)
            mx[o] = fmaxf(mx[o], __shfl_xor_sync(0xffffffffu, mx[o], off));
    int w = tid >> 5, l = tid & 31;
    if (l == 0)
        #pragma unroll
        for (int o = 0; o < 8; o++) red[w * 8 + o] = mx[o];
    __syncthreads();

    if (tid < 8) {
        float m0 = red[tid];
        #pragma unroll
        for (int ww = 1; ww < 8; ww++) m0 = fmaxf(m0, red[ww * 8 + tid]);
        sph[tid] = m0;
    }
    __syncthreads();

    // heads
    if (tid < 2) {
        int r = tid;
        float mu = bm[r], lv = bv[r];
        #pragma unroll
        for (int q = 0; q < 4; q++) {
            mu = fmaf(Wm[r * 12 + q], g_h[i * 8 + q], mu);
            lv = fmaf(Wv[r * 12 + q], g_h[i * 8 + 4 + q], lv);
        }
        #pragma unroll
        for (int q = 0; q < 8; q++) {
            mu = fmaf(Wm[r * 12 + 4 + q], sph[q], mu);
            lv = fmaf(Wv[r * 12 + 4 + q], sph[q], lv);
        }
        float e = eps[(t * N + i) * 2 + r];
        float pos = mu + e * expf(0.5f * lv);
        int base = (t * N + i) * 2 + r;
        out[base] = pos;
        out[PRED_LEN * N * 2 + base] = mu;
        out[2 * PRED_LEN * N * 2 + base] = lv;
        spos[r] = pos;
    }
    if (t == PRED_LEN - 1) return;
    __syncthreads();

    // next decoder LSTM step for agent i
    if (tid < 16) {
        int m = tid;
        float a = bd[m];
        #pragma unroll
        for (int q = 0; q < 8; q++) a = fmaf(Wd[m * 10 + q], sph[q], a);
        a = fmaf(Wd[m * 10 + 8], spos[0], a);
        a = fmaf(Wd[m * 10 + 9], spos[1], a);
        sx[m] = fmaxf(a, 0.f);
    }
    __syncthreads();
    if (tid < 32) {
        int g = tid;
        float a = bihP[g] + bhhP[g];
        #pragma unroll
        for (int m = 0; m < 16; m++) a = fmaf(WihP[g * 16 + m], sx[m], a);
        #pragma unroll
        for (int q = 0; q < 8; q++) a = fmaf(WhhP[g * 8 + q], g_h[i * 8 + q], a);
        sgate[g] = a;
    }
    __syncthreads();
    if (tid < 8) {
        int q = tid;
        float ig = sigm(sgate[q]);
        float fg = sigm(sgate[8 + q]);
        float gg = tanhf(sgate[16 + q]);
        float og = sigm(sgate[24 + q]);
        float cn = fg * g_c[i * 8 + q] + ig * gg;
        float hn = og * tanhf(cn);
        g_c[i * 8 + q] = cn;
        g_h[i * 8 + q] = hn;
        sh[q] = hn;
    }
    __syncthreads();
    if (tid < 64) {
        int k = tid;
        float pa = g_posA[i * 64 + k];
        float uu = pa, vv = g_dconst[k] - pa;
        #pragma unroll
        for (int q = 0; q < 8; q++) {
            uu = fmaf(sh[q], W1[k * 48 + 40 + q], uu);
            vv = fmaf(sh[q], W1[k * 48 + 32 + q], vv);
        }
        g_ud[i * 64 + k] = pack2(uu, uu);
        g_v[(t + 1) & 1][k * N + i] = vv;
    }
    if (tid < 8) {
        int o = tid;
        float qx = g_pos[i * 2 + 0], qy = g_pos[i * 2 + 1];
        float pp = fmaf(sPh[o * 2 + 0], qx, sPh[o * 2 + 1] * qy);
        float lin = pp, lvv = sSh[o] - pp;
        #pragma unroll
        for (int q = 0; q < 8; q++) {
            lin = fmaf(sQh[o * 8 + q], sh[q], lin);
            lvv = fmaf(sRh[o * 8 + q], sh[q], lvv);
        }
        g_lin[i * 8 + o] = lin;
        g_linvh[(t + 1) & 1][o * N + i] = lvv;
    }
}

// ---------------- launch ----------------
extern "C" void kernel_launch(void* const* d_in, const int* in_sizes, int n_in,
                              void* d_out, int out_size) {
    const float* obs_traj     = (const float*)d_in[0];
    const float* obs_traj_obs = (const float*)d_in[1];
    const int*   nei_index    = (const int*)d_in[2];
    const float* h0   = (const float*)d_in[4];
    const float* c0   = (const float*)d_in[5];
    const float* eps  = (const float*)d_in[6];
    const float* We   = (const float*)d_in[7];
    const float* be   = (const float*)d_in[8];
    const float* Wih_t = (const float*)d_in[9];
    const float* Whh_t = (const float*)d_in[10];
    const float* bih_t = (const float*)d_in[11];
    const float* bhh_t = (const float*)d_in[12];
    const float* Wd   = (const float*)d_in[13];
    const float* bd   = (const float*)d_in[14];
    const float* Wih_p = (const float*)d_in[15];
    const float* Whh_p = (const float*)d_in[16];
    const float* bih_p = (const float*)d_in[17];
    const float* bhh_p = (const float*)d_in[18];
    const float* Wsp  = (const float*)d_in[19];
    const float* bsp  = (const float*)d_in[20];
    const float* W1   = (const float*)d_in[21];
    const float* b1   = (const float*)d_in[22];
    const float* W2   = (const float*)d_in[23];
    const float* b2   = (const float*)d_in[24];
    const float* Wm   = (const float*)d_in[25];
    const float* bm   = (const float*)d_in[26];
    const float* Wv   = (const float*)d_in[27];
    const float* bv   = (const float*)d_in[28];
    float* out = (float*)d_out;

    k_setup<<<1, 64>>>(W1, b1, Wsp, bsp, W2);
    k_encoder<<<N / 128, 128>>>(obs_traj, obs_traj_obs, h0, c0, We, be,
                                Wih_t, Whh_t, bih_t, bhh_t, bd,
                                Wih_p, Whh_p, bih_p, bhh_p, W1);
    for (int t = 0; t < PRED_LEN; t++) {
        k_pool<<<N, 256>>>(nei_index, eps, b2, Wm, bm, Wv, bv,
                           Wd, bd, Wih_p, Whh_p, bih_p, bhh_p, W1, out, t);
    }
}

// round 5
// speedup vs baseline: 1.2943x; 1.2943x over previous
#include <cuda_runtime.h>
#include <math.h>

#define N 1024
#define H 8
#define OBS_LEN 8
#define PRED_LEN 12

typedef unsigned long long u64;

#define ABSMASK 0x7fffffff7fffffffULL

// ---------------- scratch (device globals; no allocation) ----------------
__device__ float g_h[N * H];
__device__ float g_c[N * H];
__device__ float g_posA[N * 64];       // posA[i][k] = A[k] . pos_i
__device__ float g_pos[N * 2];         // raw last positions
__device__ u64   g_ud[N * 64];         // (u,u) duplicated pairs, per i
__device__ float g_v[2][64 * N];       // v_j, k-major, double-buffered
__device__ float g_linvh[2][8 * N];    // 0.5*Sum_k v_jk w_ko, o-major, double-buffered
__device__ float g_lin[N * 8];         // 0.5*Sum_k u_ik w_ko
__device__ u64   g_W2d[512];           // [k][o] = (0.5*w_ko, 0.5*w_ko)  (staging)
__device__ float g_A[128];             // A[k][2] = W1[:, :32] @ Wsp
__device__ float g_dconst[64];         // d = b1 + W1[:, :32] @ bsp
__device__ float g_Ph[16];             // 0.5 * W2 @ A        [8][2]
__device__ float g_Qh[64];             // 0.5 * W2 @ C(h_i)   [8][8]
__device__ float g_Rh[64];             // 0.5 * W2 @ B(h_j)   [8][8]
__device__ float g_Sh[8];              // 0.5 * W2 @ d

// W2 table in constant bank: uniform loads go through the constant/uniform
// port (LDC/LDCU), NOT through L1tex -> removes 8 LDS wavefronts per k-iter.
__constant__ u64 c_W2[512];

// ---------------- packed f32x2 helpers ----------------
__device__ __forceinline__ u64 pack2(float lo, float hi) {
    u64 r; asm("mov.b64 %0, {%1, %2};" : "=l"(r) : "f"(lo), "f"(hi)); return r;
}
__device__ __forceinline__ void unpack2(u64 v, float& lo, float& hi) {
    asm("mov.b64 {%0, %1}, %2;" : "=f"(lo), "=f"(hi) : "l"(v));
}
__device__ __forceinline__ void ffma2(u64& d, u64 a, u64 b) {
    asm("fma.rn.f32x2 %0, %1, %2, %0;" : "+l"(d) : "l"(a), "l"(b));
}
__device__ __forceinline__ u64 add2(u64 a, u64 b) {
    u64 r; asm("add.rn.f32x2 %0, %1, %2;" : "=l"(r) : "l"(a), "l"(b)); return r;
}

__device__ __forceinline__ float sigm(float x) { return 1.f / (1.f + expf(-x)); }

// ---------------- LSTM cell helper ----------------
__device__ __forceinline__ void lstm_step(const float* x, float* h, float* c,
                                          const float* sWih, const float* sWhh,
                                          const float* sb) {
    float gates[32];
    #pragma unroll
    for (int g = 0; g < 32; g++) {
        float a = sb[g];
        #pragma unroll
        for (int m = 0; m < 16; m++) a = fmaf(sWih[g * 16 + m], x[m], a);
        #pragma unroll
        for (int q = 0; q < 8; q++) a = fmaf(sWhh[g * 8 + q], h[q], a);
        gates[g] = a;
    }
    #pragma unroll
    for (int q = 0; q < 8; q++) {
        float ig = sigm(gates[q]);
        float fg = sigm(gates[8 + q]);
        float gg = tanhf(gates[16 + q]);
        float og = sigm(gates[24 + q]);
        float cn = fg * c[q] + ig * gg;
        c[q] = cn;
        h[q] = og * tanhf(cn);
    }
}

// ---------------- setup: A, d, W2-dup table, P/Q/R/S ----------------
__global__ void k_setup(const float* __restrict__ W1, const float* __restrict__ b1,
                        const float* __restrict__ Wsp, const float* __restrict__ bsp,
                        const float* __restrict__ W2) {
    __shared__ float sA[128], sd[64];
    int t = threadIdx.x;   // 64 threads
    {
        int k = t;
        float a0 = 0.f, a1 = 0.f, dd = b1[k];
        #pragma unroll 4
        for (int e = 0; e < 32; e++) {
            float w = W1[k * 48 + e];
            a0 = fmaf(w, Wsp[e * 2 + 0], a0);
            a1 = fmaf(w, Wsp[e * 2 + 1], a1);
            dd = fmaf(w, bsp[e], dd);
        }
        sA[k * 2 + 0] = a0; sA[k * 2 + 1] = a1; sd[k] = dd;
        g_A[k * 2 + 0] = a0; g_A[k * 2 + 1] = a1; g_dconst[k] = dd;
        #pragma unroll
        for (int o = 0; o < 8; o++) {
            float w = 0.5f * W2[o * 64 + k];
            g_W2d[k * 8 + o] = pack2(w, w);
        }
    }
    __syncthreads();
    if (t < 8) {
        int o = t;
        float p0 = 0.f, p1 = 0.f, s = 0.f;
        float q[8], r[8];
        #pragma unroll
        for (int z = 0; z < 8; z++) { q[z] = 0.f; r[z] = 0.f; }
        for (int k = 0; k < 64; k++) {
            float w = 0.5f * W2[o * 64 + k];
            p0 = fmaf(w, sA[k * 2 + 0], p0);
            p1 = fmaf(w, sA[k * 2 + 1], p1);
            s  = fmaf(w, sd[k], s);
            #pragma unroll
            for (int z = 0; z < 8; z++) {
                q[z] = fmaf(w, W1[k * 48 + 40 + z], q[z]);  // C block (h_i)
                r[z] = fmaf(w, W1[k * 48 + 32 + z], r[z]);  // B block (h_j)
            }
        }
        g_Ph[o * 2 + 0] = p0; g_Ph[o * 2 + 1] = p1; g_Sh[o] = s;
        #pragma unroll
        for (int z = 0; z < 8; z++) { g_Qh[o * 8 + z] = q[z]; g_Rh[o * 8 + z] = r[z]; }
    }
}

// ---------------- encoder: 8 LSTM steps + first decoder LSTM + u/v/lin ----------------
__global__ void __launch_bounds__(128) k_encoder(
        const float* __restrict__ obs_traj, const float* __restrict__ obs_pos,
        const float* __restrict__ h0, const float* __restrict__ c0,
        const float* __restrict__ We, const float* __restrict__ be,
        const float* __restrict__ WihT, const float* __restrict__ WhhT,
        const float* __restrict__ bihT, const float* __restrict__ bhhT,
        const float* __restrict__ bd,
        const float* __restrict__ WihP, const float* __restrict__ WhhP,
        const float* __restrict__ bihP, const float* __restrict__ bhhP,
        const float* __restrict__ W1) {
    __shared__ float sWe[32], sbe[16], sWihT[512], sWhhT[256], sbT[32];
    __shared__ float sWihP[512], sWhhP[256], sbP[32], sbd[16];
    __shared__ float sB[512], sC[512], sA[128], sd[64];
    __shared__ float sPh[16], sQh[64], sRh[64], sSh[8];
    int tid = threadIdx.x;
    for (int idx = tid; idx < 32; idx += 128) sWe[idx] = We[idx];
    for (int idx = tid; idx < 16; idx += 128) { sbe[idx] = be[idx]; sbd[idx] = bd[idx];
                                               sPh[idx] = g_Ph[idx]; }
    for (int idx = tid; idx < 512; idx += 128) { sWihT[idx] = WihT[idx]; sWihP[idx] = WihP[idx]; }
    for (int idx = tid; idx < 256; idx += 128) { sWhhT[idx] = WhhT[idx]; sWhhP[idx] = WhhP[idx]; }
    for (int idx = tid; idx < 32; idx += 128) { sbT[idx] = bihT[idx] + bhhT[idx];
                                               sbP[idx] = bihP[idx] + bhhP[idx]; }
    for (int idx = tid; idx < 512; idx += 128) {
        int k = idx >> 3, q = idx & 7;
        sB[idx] = W1[k * 48 + 32 + q];
        sC[idx] = W1[k * 48 + 40 + q];
    }
    for (int idx = tid; idx < 128; idx += 128) sA[idx] = g_A[idx];
    for (int idx = tid; idx < 64; idx += 128) { sd[idx] = g_dconst[idx];
                                               sQh[idx] = g_Qh[idx]; sRh[idx] = g_Rh[idx]; }
    if (tid < 8) sSh[tid] = g_Sh[tid];
    __syncthreads();

    int i = blockIdx.x * 128 + tid;

    float h[8], c[8];
    #pragma unroll
    for (int q = 0; q < 8; q++) { h[q] = h0[i * 8 + q]; c[q] = c0[i * 8 + q]; }

    for (int t = 0; t < OBS_LEN; t++) {
        float px = obs_traj[(t * N + i) * 2 + 0];
        float py = obs_traj[(t * N + i) * 2 + 1];
        float x[16];
        #pragma unroll
        for (int m = 0; m < 16; m++)
            x[m] = fmaxf(fmaf(sWe[m * 2 + 0], px, fmaf(sWe[m * 2 + 1], py, sbe[m])), 0.f);
        lstm_step(x, h, c, sWihT, sWhhT, sbT);
    }

    // first decoder step: context=0, output=0 -> x = relu(bd)
    float x[16];
    #pragma unroll
    for (int m = 0; m < 16; m++) x[m] = fmaxf(sbd[m], 0.f);
    #pragma unroll
    for (int q = 0; q < 8; q++) c[q] = 0.f;
    lstm_step(x, h, c, sWihP, sWhhP, sbP);

    #pragma unroll
    for (int q = 0; q < 8; q++) { g_h[i * 8 + q] = h[q]; g_c[i * 8 + q] = c[q]; }

    float qx = obs_pos[((OBS_LEN - 1) * N + i) * 2 + 0];
    float qy = obs_pos[((OBS_LEN - 1) * N + i) * 2 + 1];
    g_pos[i * 2 + 0] = qx;
    g_pos[i * 2 + 1] = qy;

    #pragma unroll 4
    for (int k = 0; k < 64; k++) {
        float pa = fmaf(sA[k * 2 + 0], qx, sA[k * 2 + 1] * qy);
        g_posA[i * 64 + k] = pa;
        float uu = pa, vv = sd[k] - pa;
        #pragma unroll
        for (int q = 0; q < 8; q++) {
            uu = fmaf(h[q], sC[k * 8 + q], uu);
            vv = fmaf(h[q], sB[k * 8 + q], vv);
        }
        g_ud[i * 64 + k] = pack2(uu, uu);
        g_v[0][k * N + i] = vv;
    }

    // linear halves: lin = Ph.pos + Qh.h  ;  linvh = Sh - Ph.pos + Rh.h
    #pragma unroll
    for (int o = 0; o < 8; o++) {
        float pp = fmaf(sPh[o * 2 + 0], qx, sPh[o * 2 + 1] * qy);
        float lin = pp, lvv = sSh[o] - pp;
        #pragma unroll
        for (int q = 0; q < 8; q++) {
            lin = fmaf(sQh[o * 8 + q], h[q], lin);
            lvv = fmaf(sRh[o * 8 + q], h[q], lvv);
        }
        g_lin[i * 8 + o] = lin;
        g_linvh[0][o * N + i] = lvv;
    }
}

// ---------------- pooling + heads + next decoder step ----------------
__global__ void __launch_bounds__(256, 4) k_pool(
        const int* __restrict__ nei, const float* __restrict__ eps,
        const float* __restrict__ b2,
        const float* __restrict__ Wm, const float* __restrict__ bm,
        const float* __restrict__ Wv, const float* __restrict__ bv,
        const float* __restrict__ Wd, const float* __restrict__ bd,
        const float* __restrict__ WihP, const float* __restrict__ WhhP,
        const float* __restrict__ bihP, const float* __restrict__ bhhP,
        const float* __restrict__ W1,
        float* __restrict__ out, int t) {
    __shared__ u64 sud[64];        // (u,u) pairs for this i
    __shared__ float sbase[8];     // g_lin + b2
    __shared__ float red[64];
    __shared__ float sph[8], spos[2], sx[16], sgate[32], sh[8];
    __shared__ float sPh[16], sQh[64], sRh[64], sSh[8];

    int i = blockIdx.x;
    int tid = threadIdx.x;

    if (tid < 64) sud[tid] = g_ud[i * 64 + tid];
    if (tid < 8) sbase[tid] = g_lin[i * 8 + tid] + b2[tid];
    if (tid >= 64 && tid < 80)  sPh[tid - 64] = g_Ph[tid - 64];
    if (tid >= 80 && tid < 144) sQh[tid - 80] = g_Qh[tid - 80];
    if (tid >= 144 && tid < 208) sRh[tid - 144] = g_Rh[tid - 144];
    if (tid >= 208 && tid < 216) sSh[tid - 208] = g_Sh[tid - 208];
    __syncthreads();

    // thread handles j = 4*tid .. 4*tid+3
    // accumulators initialized with base(i,o) + linvh(j,o): epilogue-free linear part
    const float* lvb = g_linvh[t & 1];
    u64 acc01[8], acc23[8];
    #pragma unroll
    for (int o = 0; o < 8; o++) {
        float4 lv = ((const float4*)(lvb + o * N))[tid];
        float bo = sbase[o];
        acc01[o] = pack2(bo + lv.x, bo + lv.y);
        acc23[o] = pack2(bo + lv.z, bo + lv.w);
    }

    const ulonglong2* vbase = (const ulonglong2*)(g_v[t & 1]);
    #pragma unroll 8
    for (int k = 0; k < 64; k++) {
        ulonglong2 vp = vbase[k * (N / 4) + tid];
        u64 ud = sud[k];
        u64 a01 = add2(ud, vp.x) & ABSMASK;
        u64 a23 = add2(ud, vp.y) & ABSMASK;
        const u64* wr = c_W2 + k * 8;   // constant bank: uniform LDC/LDCU, off L1tex
        #pragma unroll
        for (int o = 0; o < 8; o++) {
            u64 w = wr[o];
            ffma2(acc01[o], a01, w);
            ffma2(acc23[o], a23, w);
        }
    }

    // epilogue: relu + masked max
    const int4 msk = ((const int4*)(nei + (size_t)t * N * N + (size_t)i * N))[tid];
    float mx[8];
    #pragma unroll
    for (int o = 0; o < 8; o++) {
        float a0, a1, a2, a3;
        unpack2(acc01[o], a0, a1);
        unpack2(acc23[o], a2, a3);
        float m = 0.f;
        if (msk.x > 0) m = fmaxf(m, fmaxf(a0, 0.f));
        if (msk.y > 0) m = fmaxf(m, fmaxf(a1, 0.f));
        if (msk.z > 0) m = fmaxf(m, fmaxf(a2, 0.f));
        if (msk.w > 0) m = fmaxf(m, fmaxf(a3, 0.f));
        mx[o] = m;
    }

    #pragma unroll
    for (int off = 16; off > 0; off >>= 1)
        #pragma unroll
        for (int o = 0; o < 8; o++)
            mx[o] = fmaxf(mx[o], __shfl_xor_sync(0xffffffffu, mx[o], off));
    int w = tid >> 5, l = tid & 31;
    if (l == 0)
        #pragma unroll
        for (int o = 0; o < 8; o++) red[w * 8 + o] = mx[o];
    __syncthreads();

    if (tid < 8) {
        float m0 = red[tid];
        #pragma unroll
        for (int ww = 1; ww < 8; ww++) m0 = fmaxf(m0, red[ww * 8 + tid]);
        sph[tid] = m0;
    }
    __syncthreads();

    // heads
    if (tid < 2) {
        int r = tid;
        float mu = bm[r], lv = bv[r];
        #pragma unroll
        for (int q = 0; q < 4; q++) {
            mu = fmaf(Wm[r * 12 + q], g_h[i * 8 + q], mu);
            lv = fmaf(Wv[r * 12 + q], g_h[i * 8 + 4 + q], lv);
        }
        #pragma unroll
        for (int q = 0; q < 8; q++) {
            mu = fmaf(Wm[r * 12 + 4 + q], sph[q], mu);
            lv = fmaf(Wv[r * 12 + 4 + q], sph[q], lv);
        }
        float e = eps[(t * N + i) * 2 + r];
        float pos = mu + e * expf(0.5f * lv);
        int base = (t * N + i) * 2 + r;
        out[base] = pos;
        out[PRED_LEN * N * 2 + base] = mu;
        out[2 * PRED_LEN * N * 2 + base] = lv;
        spos[r] = pos;
    }
    if (t == PRED_LEN - 1) return;
    __syncthreads();

    // next decoder LSTM step for agent i
    if (tid < 16) {
        int m = tid;
        float a = bd[m];
        #pragma unroll
        for (int q = 0; q < 8; q++) a = fmaf(Wd[m * 10 + q], sph[q], a);
        a = fmaf(Wd[m * 10 + 8], spos[0], a);
        a = fmaf(Wd[m * 10 + 9], spos[1], a);
        sx[m] = fmaxf(a, 0.f);
    }
    __syncthreads();
    if (tid < 32) {
        int g = tid;
        float a = bihP[g] + bhhP[g];
        #pragma unroll
        for (int m = 0; m < 16; m++) a = fmaf(WihP[g * 16 + m], sx[m], a);
        #pragma unroll
        for (int q = 0; q < 8; q++) a = fmaf(WhhP[g * 8 + q], g_h[i * 8 + q], a);
        sgate[g] = a;
    }
    __syncthreads();
    if (tid < 8) {
        int q = tid;
        float ig = sigm(sgate[q]);
        float fg = sigm(sgate[8 + q]);
        float gg = tanhf(sgate[16 + q]);
        float og = sigm(sgate[24 + q]);
        float cn = fg * g_c[i * 8 + q] + ig * gg;
        float hn = og * tanhf(cn);
        g_c[i * 8 + q] = cn;
        g_h[i * 8 + q] = hn;
        sh[q] = hn;
    }
    __syncthreads();
    if (tid < 64) {
        int k = tid;
        float pa = g_posA[i * 64 + k];
        float uu = pa, vv = g_dconst[k] - pa;
        #pragma unroll
        for (int q = 0; q < 8; q++) {
            uu = fmaf(sh[q], W1[k * 48 + 40 + q], uu);
            vv = fmaf(sh[q], W1[k * 48 + 32 + q], vv);
        }
        g_ud[i * 64 + k] = pack2(uu, uu);
        g_v[(t + 1) & 1][k * N + i] = vv;
    }
    if (tid < 8) {
        int o = tid;
        float qx = g_pos[i * 2 + 0], qy = g_pos[i * 2 + 1];
        float pp = fmaf(sPh[o * 2 + 0], qx, sPh[o * 2 + 1] * qy);
        float lin = pp, lvv = sSh[o] - pp;
        #pragma unroll
        for (int q = 0; q < 8; q++) {
            lin = fmaf(sQh[o * 8 + q], sh[q], lin);
            lvv = fmaf(sRh[o * 8 + q], sh[q], lvv);
        }
        g_lin[i * 8 + o] = lin;
        g_linvh[(t + 1) & 1][o * N + i] = lvv;
    }
}

// ---------------- launch ----------------
extern "C" void kernel_launch(void* const* d_in, const int* in_sizes, int n_in,
                              void* d_out, int out_size) {
    const float* obs_traj     = (const float*)d_in[0];
    const float* obs_traj_obs = (const float*)d_in[1];
    const int*   nei_index    = (const int*)d_in[2];
    const float* h0   = (const float*)d_in[4];
    const float* c0   = (const float*)d_in[5];
    const float* eps  = (const float*)d_in[6];
    const float* We   = (const float*)d_in[7];
    const float* be   = (const float*)d_in[8];
    const float* Wih_t = (const float*)d_in[9];
    const float* Whh_t = (const float*)d_in[10];
    const float* bih_t = (const float*)d_in[11];
    const float* bhh_t = (const float*)d_in[12];
    const float* Wd   = (const float*)d_in[13];
    const float* bd   = (const float*)d_in[14];
    const float* Wih_p = (const float*)d_in[15];
    const float* Whh_p = (const float*)d_in[16];
    const float* bih_p = (const float*)d_in[17];
    const float* bhh_p = (const float*)d_in[18];
    const float* Wsp  = (const float*)d_in[19];
    const float* bsp  = (const float*)d_in[20];
    const float* W1   = (const float*)d_in[21];
    const float* b1   = (const float*)d_in[22];
    const float* W2   = (const float*)d_in[23];
    const float* b2   = (const float*)d_in[24];
    const float* Wm   = (const float*)d_in[25];
    const float* bm   = (const float*)d_in[26];
    const float* Wv   = (const float*)d_in[27];
    const float* bv   = (const float*)d_in[28];
    float* out = (float*)d_out;

    k_setup<<<1, 64>>>(W1, b1, Wsp, bsp, W2);

    // stage the W2 table into the constant bank (D2D copy; graph-capturable)
    void* w2src = nullptr;
    cudaGetSymbolAddress(&w2src, g_W2d);
    cudaMemcpyToSymbolAsync(c_W2, w2src, 512 * sizeof(u64), 0,
                            cudaMemcpyDeviceToDevice, 0);

    k_encoder<<<N / 128, 128>>>(obs_traj, obs_traj_obs, h0, c0, We, be,
                                Wih_t, Whh_t, bih_t, bhh_t, bd,
                                Wih_p, Whh_p, bih_p, bhh_p, W1);
    for (int t = 0; t < PRED_LEN; t++) {
        k_pool<<<N, 256>>>(nei_index, eps, b2, Wm, bm, Wv, bv,
                           Wd, bd, Wih_p, Whh_p, bih_p, bhh_p, W1, out, t);
    }
}